// round 12
// baseline (speedup 1.0000x reference)
#include <cuda_runtime.h>
#include <cuda_fp16.h>
#include <cstdint>

// ---------------------------------------------------------------------------
// Problem constants
// ---------------------------------------------------------------------------
#define KDIM 256
#define NDIM 256
#define KC   64                    // K chunk
#define NCHUNK (KDIM / KC)
#define NTHR 512                   // 16 warps
#define BM 128                     // M-block rows
#define GRID_MAIN 148              // persistent: 1 CTA per SM

// SMEM layout (bytes)
#define OFF_STAB  0                              // 8 x float4 = 128B
#define OFF_CTAB  128                            // padded (c0,c1) pairs
#define OFF_A     3072                           // 1024-aligned
#define A_BUF     (BM * 128)                     // 16384
#define OFF_B     (OFF_A + 2 * A_BUF)            // 35840 (1024-aligned)
#define B_CHUNK   (NDIM * 128)                   // 32768
#define SMEM_TOTAL (OFF_B + NCHUNK * B_CHUNK)    // 166912 (~163KB, 1 CTA/SM)

// ---------------------------------------------------------------------------
// Prologue outputs
// ---------------------------------------------------------------------------
__device__ __align__(16) unsigned char g_Bf[NCHUNK][NDIM * 128];  // swizzled fp16
__device__ __align__(16) unsigned char g_ctab[2432];              // padded c0c1
__device__ __align__(16) float4 g_stab[8];                        // segment cubics

// ---------------------------------------------------------------------------
// helpers
// ---------------------------------------------------------------------------
__device__ __forceinline__ uint32_t smem_u32(const void* p) {
    uint32_t a;
    asm("{ .reg .u64 t; cvta.to.shared.u64 t, %1; cvt.u32.u64 %0, t; }" : "=r"(a) : "l"(p));
    return a;
}

__device__ __forceinline__ void ldsm_x4(uint32_t& r0, uint32_t& r1, uint32_t& r2,
                                        uint32_t& r3, uint32_t addr) {
    asm volatile("ldmatrix.sync.aligned.m8n8.x4.shared.b16 {%0,%1,%2,%3}, [%4];"
                 : "=r"(r0), "=r"(r1), "=r"(r2), "=r"(r3) : "r"(addr));
}

__device__ __forceinline__ void mma_fp16(float* c, const uint32_t* a,
                                         uint32_t b0, uint32_t b1) {
    asm volatile(
        "mma.sync.aligned.m16n8k16.row.col.f32.f16.f16.f32 "
        "{%0,%1,%2,%3}, {%4,%5,%6,%7}, {%8,%9}, {%0,%1,%2,%3};"
        : "+f"(c[0]), "+f"(c[1]), "+f"(c[2]), "+f"(c[3])
        : "r"(a[0]), "r"(a[1]), "r"(a[2]), "r"(a[3]), "r"(b0), "r"(b1));
}

#define CP_ASYNC16(saddr, gptr) \
    asm volatile("cp.async.cg.shared.global [%0], [%1], 16;" :: "r"(saddr), "l"(gptr))
#define CP_COMMIT() asm volatile("cp.async.commit_group;")
#define CP_WAIT0()  asm volatile("cp.async.wait_group 0;")

__device__ __forceinline__ uint32_t pack_h2(float a0, float a1) {
    __half2 h = __floats2half2_rn(a0, a1);
    return *reinterpret_cast<uint32_t*>(&h);
}

__device__ __host__ __forceinline__ int ctab_off(int k) {
    return k * 8 + (k >> 4) * 16;
}

// ---------------------------------------------------------------------------
// Prologue: fp16 pre-swizzled B images + c0c1 pairs + segment-cubic table
// ---------------------------------------------------------------------------
__global__ void kan_prologue(const float* __restrict__ ic, const float* __restrict__ oc) {
    if (blockIdx.x < 32) {
        int gid = blockIdx.x * 256 + threadIdx.x;   // 0..8191
        int n   = gid >> 5;                          // B row 0..255
        int g   = gid & 31;                          // k-granule (8 fp32)
        int chunk = g >> 3;
        int colg  = g & 7;
        const float4* src = (const float4*)(oc + n * KDIM + g * 8);
        float4 v0 = src[0], v1 = src[1];
        float a[8] = {v0.x, v0.y, v0.z, v0.w, v1.x, v1.y, v1.z, v1.w};
        uint32_t h[4];
#pragma unroll
        for (int e = 0; e < 4; e++) h[e] = pack_h2(a[2 * e], a[2 * e + 1]);
        int off = n * 128 + ((colg ^ (n & 7)) << 4);
        *(uint4*)(g_Bf[chunk] + off) = make_uint4(h[0], h[1], h[2], h[3]);
    } else {
        int k = threadIdx.x;
        float c0 = ic[k * 5 + 0];
        float c1 = ic[k * 5 + 1];
        *(float2*)(g_ctab + ctab_off(k)) = make_float2(c0, c1);
        if (k < 8) {
            const float P[4][4] = {
                {0.f, 0.f, 0.f,  1.f},
                {1.f, 3.f, 3.f, -3.f},
                {4.f, 0.f, -6.f, 3.f},
                {1.f, -3.f, 3.f, -1.f}
            };
            float4 s = make_float4(0.f, 0.f, 0.f, 0.f);
            if (k >= 1 && k <= 4) {
                const float s6 = 1.0f / 6.0f;
                int m = k - 1;
                s = make_float4(P[m][0] * s6, P[m][1] * s6, P[m][2] * s6, P[m][3] * s6);
            }
            g_stab[k] = s;
        }
    }
}

// ---------------------------------------------------------------------------
// Hot-path activation (validated R10 variant, conflict-free)
// ---------------------------------------------------------------------------
__device__ __forceinline__ float kan_act2(float xv, float c0, float c1,
                                          const float4* __restrict__ stab) {
    float e2 = __expf(2.0f * xv);
    float t  = 1.0f - __fdividef(2.0f, e2 + 1.0f);   // tanh
    float v  = fmaf(t, 3.5f, 3.5f);                   // (t+1)/h, in [0,7]
    int j = (int)v;
    j = j > 5 ? 5 : j;
    float u = v - (float)j;
    float4 sB = stab[j];
    float4 sA = stab[j + 1];
    float b30 = fmaf(fmaf(fmaf(sA.w, u, sA.z), u, sA.y), u, sA.x);
    float b31 = fmaf(fmaf(fmaf(sB.w, u, sB.z), u, sB.y), u, sB.x);
    return fmaf(c0, b30, c1 * b31);
}

__device__ __forceinline__ void act16(const float* av, int kb, const char* ctab,
                                      const float4* __restrict__ stab, float* r) {
#pragma unroll
    for (int p = 0; p < 8; p++) {
        int k0 = kb + 2 * p;
        float4 cg = *(const float4*)(ctab + ctab_off(k0));
        r[2 * p]     = kan_act2(av[2 * p],     cg.x, cg.y, stab);
        r[2 * p + 1] = kan_act2(av[2 * p + 1], cg.z, cg.w, stab);
    }
}

// ---------------------------------------------------------------------------
// Main: persistent CTA (1/SM). B (all 4 chunks, 128KB) resident in smem,
// loaded once. Grid-stride loop over M-blocks of 128 rows; per block the
// validated act/A-dbuf/HMMA pipeline with zero in-loop cp.async.
// ---------------------------------------------------------------------------
__global__ void __launch_bounds__(NTHR, 1)
kan_main(const float* __restrict__ x, float* __restrict__ out, int nblocks) {
    extern __shared__ __align__(1024) char smem[];
    const int tid = threadIdx.x;
    const int wid = tid >> 5;
    const int lid = tid & 31;

    const uint32_t sbase = smem_u32(smem);

    // warp tile: 32 (M) x 64 (N); 16 warps = 4 (M) x 4 (N)
    const int wm = (wid >> 2) * 32;
    const int wn = (wid & 3) * 64;

    // ---- stage tables ----
    if (tid < 160) {
        if (tid < 8)
            ((float4*)(smem + OFF_STAB))[tid] = g_stab[tid];
        else
            ((float4*)(smem + OFF_CTAB))[tid - 8] = ((const float4*)g_ctab)[tid - 8];
    }
    // ---- load ALL of B once (128KB, 16 cp.async per thread) ----
    {
        const char* src = (const char*)g_Bf;
        uint32_t dst = sbase + OFF_B;
#pragma unroll
        for (int i = 0; i < 16; i++) {
            int idx = tid + i * NTHR;                // 0..8191 granules
            CP_ASYNC16(dst + idx * 16, src + idx * 16);
        }
        CP_COMMIT();
    }
    CP_WAIT0();
    __syncthreads();                     // tables + B visible

    const float4* stab = (const float4*)(smem + OFF_STAB);
    const char*   ctab = smem + OFF_CTAB;

    // per-thread activation geometry (128 rows / 512 threads)
    const int arow = tid >> 2;          // 0..127
    const int aq   = tid & 3;           // k-quarter (16 elems)
    const int swg0 = ((aq * 2)     ^ (arow & 7)) << 4;
    const int swg1 = ((aq * 2 + 1) ^ (arow & 7)) << 4;

    const int lr   = lid & 15;
    const int lhal = lid >> 4;

    // ---- persistent loop over M-blocks ----
    for (int mb = blockIdx.x; mb < nblocks; mb += GRID_MAIN) {
        const int m0 = mb * BM;
        const float4* xbase = (const float4*)(x + (size_t)(m0 + arow) * KDIM + aq * 16);
        float4 xv0 = xbase[0], xv1 = xbase[1], xv2 = xbase[2], xv3 = xbase[3];

        // act(0) -> A buf 0  (safe: A0 last read at MMA(2) of prev block,
        // which all warps passed at the bar before its MMA(3))
        {
            float av[16] = {xv0.x, xv0.y, xv0.z, xv0.w, xv1.x, xv1.y, xv1.z, xv1.w,
                            xv2.x, xv2.y, xv2.z, xv2.w, xv3.x, xv3.y, xv3.z, xv3.w};
            float r[16];
            act16(av, aq * 16, ctab, stab, r);
            char* ad = smem + OFF_A + arow * 128;
            *(uint4*)(ad + swg0) = make_uint4(pack_h2(r[0], r[1]),  pack_h2(r[2], r[3]),
                                              pack_h2(r[4], r[5]),  pack_h2(r[6], r[7]));
            *(uint4*)(ad + swg1) = make_uint4(pack_h2(r[8], r[9]),  pack_h2(r[10], r[11]),
                                              pack_h2(r[12], r[13]), pack_h2(r[14], r[15]));
        }

        float acc[2][8][4];
#pragma unroll
        for (int mt = 0; mt < 2; mt++)
#pragma unroll
            for (int nt = 0; nt < 8; nt++)
#pragma unroll
                for (int e = 0; e < 4; e++) acc[mt][nt][e] = 0.0f;

#pragma unroll
        for (int c = 0; c < NCHUNK; c++) {
            const int s = c & 1;
            __syncthreads();             // A(c) visible; A(alt) readers done

            // prefetch x(c+1)
            if (c < NCHUNK - 1) {
                const float4* xp = xbase + (c + 1) * (KC / 4);
                xv0 = xp[0]; xv1 = xp[1]; xv2 = xp[2]; xv3 = xp[3];
            }

            // MMA(c): 4 ksteps from resident B chunk c
            const uint32_t aBase = sbase + OFF_A + s * A_BUF;
            const uint32_t bBase = sbase + OFF_B + c * B_CHUNK;
#pragma unroll
            for (int ks = 0; ks < 4; ks++) {
                const int g = ks * 2 + lhal;
                uint32_t a[2][4];
#pragma unroll
                for (int mt = 0; mt < 2; mt++) {
                    int r = wm + mt * 16 + lr;
                    uint32_t off = (uint32_t)(r * 128 + ((g ^ (r & 7)) << 4));
                    ldsm_x4(a[mt][0], a[mt][1], a[mt][2], a[mt][3], aBase + off);
                }
#pragma unroll
                for (int np = 0; np < 4; np++) {
                    int r = wn + np * 16 + lr;
                    uint32_t off = (uint32_t)(r * 128 + ((g ^ (r & 7)) << 4));
                    uint32_t b[4];
                    ldsm_x4(b[0], b[1], b[2], b[3], bBase + off);
#pragma unroll
                    for (int mt = 0; mt < 2; mt++) {
                        mma_fp16(acc[mt][2 * np + 0], a[mt], b[0], b[2]);
                        mma_fp16(acc[mt][2 * np + 1], a[mt], b[1], b[3]);
                    }
                }
            }

            // act(c+1) -> other A buffer
            if (c < NCHUNK - 1) {
                float av[16] = {xv0.x, xv0.y, xv0.z, xv0.w, xv1.x, xv1.y, xv1.z, xv1.w,
                                xv2.x, xv2.y, xv2.z, xv2.w, xv3.x, xv3.y, xv3.z, xv3.w};
                float r[16];
                act16(av, (c + 1) * KC + aq * 16, ctab, stab, r);
                char* ad = smem + OFF_A + (s ^ 1) * A_BUF + arow * 128;
                *(uint4*)(ad + swg0) = make_uint4(pack_h2(r[0], r[1]),  pack_h2(r[2], r[3]),
                                                  pack_h2(r[4], r[5]),  pack_h2(r[6], r[7]));
                *(uint4*)(ad + swg1) = make_uint4(pack_h2(r[8], r[9]),  pack_h2(r[10], r[11]),
                                                  pack_h2(r[12], r[13]), pack_h2(r[14], r[15]));
            }
        }

        // epilogue: direct fp32 stores
        {
            const int rq = lid >> 2;
            const int cq = (lid & 3) * 2;
#pragma unroll
            for (int mt = 0; mt < 2; mt++) {
                int row = m0 + wm + mt * 16 + rq;
#pragma unroll
                for (int nt = 0; nt < 8; nt++) {
                    int col = wn + nt * 8 + cq;
                    float2 v0 = make_float2(acc[mt][nt][0], acc[mt][nt][1]);
                    float2 v1 = make_float2(acc[mt][nt][2], acc[mt][nt][3]);
                    *(float2*)(out + (size_t)row * NDIM + col)       = v0;
                    *(float2*)(out + (size_t)(row + 8) * NDIM + col) = v1;
                }
            }
        }
    }
}

// ---------------------------------------------------------------------------
extern "C" void kernel_launch(void* const* d_in, const int* in_sizes, int n_in,
                              void* d_out, int out_size) {
    const float* x  = (const float*)d_in[0];   // [B,S,256] fp32
    const float* ic = (const float*)d_in[1];   // [256,5]   fp32
    const float* oc = (const float*)d_in[2];   // [256,256] fp32
    float* out = (float*)d_out;

    const int M = in_sizes[0] / KDIM;          // 65536
    const int nblocks = M / BM;                // 512

    cudaFuncSetAttribute(kan_main, cudaFuncAttributeMaxDynamicSharedMemorySize, SMEM_TOTAL);

    kan_prologue<<<33, 256>>>(ic, oc);
    kan_main<<<GRID_MAIN, NTHR, SMEM_TOTAL>>>(x, out, nblocks);
}

// round 13
// speedup vs baseline: 1.1484x; 1.1484x over previous
#include <cuda_runtime.h>
#include <cuda_fp16.h>
#include <cstdint>

// ---------------------------------------------------------------------------
// Problem constants
// ---------------------------------------------------------------------------
#define KDIM 256
#define NDIM 256
#define KC   64                    // K chunk
#define NCHUNK (KDIM / KC)
#define NTHR 256                   // 8 warps
#define BM 64                      // CTA M tile (2 CTAs/SM)

// SMEM layout (bytes)
#define OFF_STAB  0                              // 8 x float4 = 128B
#define OFF_CTAB  128                            // padded (c0,c1) pairs
#define OFF_A     3072                           // 1024-aligned
#define A_BUF     (BM * 128)                     // 8192
#define OFF_B     (OFF_A + 2 * A_BUF)            // 19456
#define B_BUF     (256 * 128)                    // 32768
#define SMEM_TOTAL (OFF_B + 2 * B_BUF)           // 84992 (x2 CTAs = 166KB/SM)

#define MAGIC   12582912.0f        /* 1.5 * 2^23 */
#define MAGIC_I 0x4B400000

// ---------------------------------------------------------------------------
// Prologue outputs
// ---------------------------------------------------------------------------
__device__ __align__(16) unsigned char g_Bf[NCHUNK][NDIM * 128];
__device__ __align__(16) unsigned char g_ctab[2432];   // padded c0c1 image
__device__ __align__(16) float4 g_stab[8];             // segment cubics

// ---------------------------------------------------------------------------
// helpers
// ---------------------------------------------------------------------------
__device__ __forceinline__ uint32_t smem_u32(const void* p) {
    uint32_t a;
    asm("{ .reg .u64 t; cvta.to.shared.u64 t, %1; cvt.u32.u64 %0, t; }" : "=r"(a) : "l"(p));
    return a;
}

__device__ __forceinline__ void ldsm_x4(uint32_t& r0, uint32_t& r1, uint32_t& r2,
                                        uint32_t& r3, uint32_t addr) {
    asm volatile("ldmatrix.sync.aligned.m8n8.x4.shared.b16 {%0,%1,%2,%3}, [%4];"
                 : "=r"(r0), "=r"(r1), "=r"(r2), "=r"(r3) : "r"(addr));
}

__device__ __forceinline__ void mma_fp16(float* c, const uint32_t* a,
                                         uint32_t b0, uint32_t b1) {
    asm volatile(
        "mma.sync.aligned.m16n8k16.row.col.f32.f16.f16.f32 "
        "{%0,%1,%2,%3}, {%4,%5,%6,%7}, {%8,%9}, {%0,%1,%2,%3};"
        : "+f"(c[0]), "+f"(c[1]), "+f"(c[2]), "+f"(c[3])
        : "r"(a[0]), "r"(a[1]), "r"(a[2]), "r"(a[3]), "r"(b0), "r"(b1));
}

#define CP_ASYNC16(saddr, gptr) \
    asm volatile("cp.async.cg.shared.global [%0], [%1], 16;" :: "r"(saddr), "l"(gptr))
#define CP_COMMIT() asm volatile("cp.async.commit_group;")
#define CP_WAIT0()  asm volatile("cp.async.wait_group 0;")

__device__ __forceinline__ uint32_t pack_h2(float a0, float a1) {
    __half2 h = __floats2half2_rn(a0, a1);
    return *reinterpret_cast<uint32_t*>(&h);
}

__device__ __host__ __forceinline__ int ctab_off(int k) {
    return k * 8 + (k >> 4) * 16;
}

// ---------------------------------------------------------------------------
// Prologue: fp16 pre-swizzled B images + c0c1 pairs + segment-cubic table
// ---------------------------------------------------------------------------
__global__ void kan_prologue(const float* __restrict__ ic, const float* __restrict__ oc) {
    if (blockIdx.x < 32) {
        int gid = blockIdx.x * 256 + threadIdx.x;   // 0..8191
        int n   = gid >> 5;                          // B row 0..255
        int g   = gid & 31;                          // k-granule (8 fp32)
        int chunk = g >> 3;
        int colg  = g & 7;
        const float4* src = (const float4*)(oc + n * KDIM + g * 8);
        float4 v0 = src[0], v1 = src[1];
        float a[8] = {v0.x, v0.y, v0.z, v0.w, v1.x, v1.y, v1.z, v1.w};
        uint32_t h[4];
#pragma unroll
        for (int e = 0; e < 4; e++) h[e] = pack_h2(a[2 * e], a[2 * e + 1]);
        int off = n * 128 + ((colg ^ (n & 7)) << 4);
        *(uint4*)(g_Bf[chunk] + off) = make_uint4(h[0], h[1], h[2], h[3]);
    } else {
        int k = threadIdx.x;
        float c0 = ic[k * 5 + 0];
        float c1 = ic[k * 5 + 1];
        *(float2*)(g_ctab + ctab_off(k)) = make_float2(c0, c1);
        if (k < 8) {
            const float P[4][4] = {
                {0.f, 0.f, 0.f,  1.f},
                {1.f, 3.f, 3.f, -3.f},
                {4.f, 0.f, -6.f, 3.f},
                {1.f, -3.f, 3.f, -1.f}
            };
            float4 s = make_float4(0.f, 0.f, 0.f, 0.f);
            if (k >= 1 && k <= 4) {
                const float s6 = 1.0f / 6.0f;
                int m = k - 1;
                s = make_float4(P[m][0] * s6, P[m][1] * s6, P[m][2] * s6, P[m][3] * s6);
            }
            g_stab[k] = s;
        }
    }
}

// ---------------------------------------------------------------------------
// Hot-path activation: v = 7 - 7/(e^{2x}+1); magic-number floor; segment cubics
// ---------------------------------------------------------------------------
__device__ __forceinline__ float kan_act2(float xv, float c0, float c1,
                                          const float4* __restrict__ stab) {
    float e2 = __expf(2.0f * xv);
    float v  = 7.0f - __fdividef(7.0f, e2 + 1.0f);   // = 3.5*(tanh(x)+1), in (0,7)
    float wf = __fadd_rz(v, MAGIC);                   // floor via RZ magic
    int   j  = __float_as_int(wf) - MAGIC_I;
    float jf = wf - MAGIC;
    j  = j > 5 ? 5 : j;
    jf = fminf(jf, 5.0f);
    float u = v - jf;
    float4 sB = stab[j];        // B31 segment cubic
    float4 sA = stab[j + 1];    // B30 segment cubic
    float b30 = fmaf(fmaf(fmaf(sA.w, u, sA.z), u, sA.y), u, sA.x);
    float b31 = fmaf(fmaf(fmaf(sB.w, u, sB.z), u, sB.y), u, sB.x);
    return fmaf(c0, b30, c1 * b31);
}

__device__ __forceinline__ void act16(const float* av, int kb, const char* ctab,
                                      const float4* __restrict__ stab, float* r) {
#pragma unroll
    for (int p = 0; p < 8; p++) {
        int k0 = kb + 2 * p;
        float4 cg = *(const float4*)(ctab + ctab_off(k0));
        r[2 * p]     = kan_act2(av[2 * p],     cg.x, cg.y, stab);
        r[2 * p + 1] = kan_act2(av[2 * p + 1], cg.z, cg.w, stab);
    }
}

// ---------------------------------------------------------------------------
// Main: CTA computes C[64 x 256] = act(X[64 x 256]) @ W^T, fp16 HMMA.
// R10 pipeline; act micro-opts + B-ldsm software pipelining.
// ---------------------------------------------------------------------------
__global__ void __launch_bounds__(NTHR, 2)
kan_main(const float* __restrict__ x, float* __restrict__ out) {
    extern __shared__ __align__(1024) char smem[];
    const int tid = threadIdx.x;
    const int wid = tid >> 5;
    const int lid = tid & 31;
    const int m0  = blockIdx.x * BM;

    const uint32_t sbase = smem_u32(smem);

    // warp tile: 32 (M) x 64 (N); 8 warps = 2 (M) x 4 (N)
    const int wm = (wid >> 2) * 32;
    const int wn = (wid & 3) * 64;

    // ---- stage tables ----
    if (tid < 160) {
        if (tid < 8)
            ((float4*)(smem + OFF_STAB))[tid] = g_stab[tid];
        else
            ((float4*)(smem + OFF_CTAB))[tid - 8] = ((const float4*)g_ctab)[tid - 8];
    }
    // ---- issue B chunk 0 ----
    {
        uint32_t dh = sbase + OFF_B;
#pragma unroll
        for (int i = 0; i < 8; i++) {
            int idx = tid + i * NTHR;                // 0..2047 granules
            CP_ASYNC16(dh + idx * 16, (const char*)g_Bf[0] + idx * 16);
        }
        CP_COMMIT();
    }

    // ---- x chunk 0 ----
    const int arow = tid >> 2;          // 0..63
    const int aq   = tid & 3;           // k-quarter (16 elems)
    const float4* xbase = (const float4*)(x + (size_t)(m0 + arow) * KDIM + aq * 16);
    float4 xv0 = xbase[0], xv1 = xbase[1], xv2 = xbase[2], xv3 = xbase[3];

    __syncthreads();                    // tables visible
    const float4* stab = (const float4*)(smem + OFF_STAB);
    const char*   ctab = smem + OFF_CTAB;

    const int swg0 = ((aq * 2)     ^ (arow & 7)) << 4;
    const int swg1 = ((aq * 2 + 1) ^ (arow & 7)) << 4;

    // ---- act(0) -> A buf 0 ----
    {
        float av[16] = {xv0.x, xv0.y, xv0.z, xv0.w, xv1.x, xv1.y, xv1.z, xv1.w,
                        xv2.x, xv2.y, xv2.z, xv2.w, xv3.x, xv3.y, xv3.z, xv3.w};
        float r[16];
        act16(av, aq * 16, ctab, stab, r);
        char* ad = smem + OFF_A + arow * 128;
        *(uint4*)(ad + swg0) = make_uint4(pack_h2(r[0], r[1]),  pack_h2(r[2], r[3]),
                                          pack_h2(r[4], r[5]),  pack_h2(r[6], r[7]));
        *(uint4*)(ad + swg1) = make_uint4(pack_h2(r[8], r[9]),  pack_h2(r[10], r[11]),
                                          pack_h2(r[12], r[13]), pack_h2(r[14], r[15]));
    }

    float acc[2][8][4];
#pragma unroll
    for (int mt = 0; mt < 2; mt++)
#pragma unroll
        for (int nt = 0; nt < 8; nt++)
#pragma unroll
            for (int e = 0; e < 4; e++) acc[mt][nt][e] = 0.0f;

    const int lr   = lid & 15;          // ldmatrix row within 16
    const int lhal = lid >> 4;          // k-granule half

#pragma unroll
    for (int c = 0; c < NCHUNK; c++) {
        const int s = c & 1;

        CP_WAIT0();                     // B(c) landed (only group in flight)
        __syncthreads();                // A(c)+B(c) visible; MMA(c-1) reads done

        // ---- prefetch chunk c+1: B via cp.async, x via LDG ----
        if (c < NCHUNK - 1) {
            uint32_t dh = sbase + OFF_B + (s ^ 1) * B_BUF;
#pragma unroll
            for (int i = 0; i < 8; i++) {
                int idx = tid + i * NTHR;
                CP_ASYNC16(dh + idx * 16, (const char*)g_Bf[c + 1] + idx * 16);
            }
            CP_COMMIT();
            const float4* xp = xbase + (c + 1) * (KC / 4);
            xv0 = xp[0]; xv1 = xp[1]; xv2 = xp[2]; xv3 = xp[3];
        }

        // ---- MMA(c): 4 ksteps; B-ldsm pipelined by one np ----
        const uint32_t aBase = sbase + OFF_A + s * A_BUF;
        const uint32_t bBase = sbase + OFF_B + s * B_BUF;
#pragma unroll
        for (int ks = 0; ks < 4; ks++) {
            const int g = ks * 2 + lhal;
            uint32_t a[2][4];
#pragma unroll
            for (int mt = 0; mt < 2; mt++) {
                int r = wm + mt * 16 + lr;
                uint32_t off = (uint32_t)(r * 128 + ((g ^ (r & 7)) << 4));
                ldsm_x4(a[mt][0], a[mt][1], a[mt][2], a[mt][3], aBase + off);
            }
            uint32_t b[2][4];
            {
                int r = wn + lr;        // np = 0
                uint32_t off = (uint32_t)(r * 128 + ((g ^ (r & 7)) << 4));
                ldsm_x4(b[0][0], b[0][1], b[0][2], b[0][3], bBase + off);
            }
#pragma unroll
            for (int np = 0; np < 4; np++) {
                const int pb = np & 1;
                if (np < 3) {           // prefetch b(np+1) before mma(np)
                    int r = wn + (np + 1) * 16 + lr;
                    uint32_t off = (uint32_t)(r * 128 + ((g ^ (r & 7)) << 4));
                    ldsm_x4(b[pb ^ 1][0], b[pb ^ 1][1], b[pb ^ 1][2], b[pb ^ 1][3],
                            bBase + off);
                }
#pragma unroll
                for (int mt = 0; mt < 2; mt++) {
                    mma_fp16(acc[mt][2 * np + 0], a[mt], b[pb][0], b[pb][2]);
                    mma_fp16(acc[mt][2 * np + 1], a[mt], b[pb][1], b[pb][3]);
                }
            }
        }

        // ---- act(c+1) -> other A buffer ----
        if (c < NCHUNK - 1) {
            float av[16] = {xv0.x, xv0.y, xv0.z, xv0.w, xv1.x, xv1.y, xv1.z, xv1.w,
                            xv2.x, xv2.y, xv2.z, xv2.w, xv3.x, xv3.y, xv3.z, xv3.w};
            float r[16];
            act16(av, (c + 1) * KC + aq * 16, ctab, stab, r);
            char* ad = smem + OFF_A + (s ^ 1) * A_BUF + arow * 128;
            *(uint4*)(ad + swg0) = make_uint4(pack_h2(r[0], r[1]),  pack_h2(r[2], r[3]),
                                              pack_h2(r[4], r[5]),  pack_h2(r[6], r[7]));
            *(uint4*)(ad + swg1) = make_uint4(pack_h2(r[8], r[9]),  pack_h2(r[10], r[11]),
                                              pack_h2(r[12], r[13]), pack_h2(r[14], r[15]));
        }
    }

    // ---- epilogue: direct fp32 stores from accumulators ----
    {
        const int rq = lid >> 2;            // 0..7
        const int cq = (lid & 3) * 2;       // 0,2,4,6
#pragma unroll
        for (int mt = 0; mt < 2; mt++) {
            int row = m0 + wm + mt * 16 + rq;
#pragma unroll
            for (int nt = 0; nt < 8; nt++) {
                int col = wn + nt * 8 + cq;
                float2 v0 = make_float2(acc[mt][nt][0], acc[mt][nt][1]);
                float2 v1 = make_float2(acc[mt][nt][2], acc[mt][nt][3]);
                *(float2*)(out + (size_t)row * NDIM + col)       = v0;
                *(float2*)(out + (size_t)(row + 8) * NDIM + col) = v1;
            }
        }
    }
}

// ---------------------------------------------------------------------------
extern "C" void kernel_launch(void* const* d_in, const int* in_sizes, int n_in,
                              void* d_out, int out_size) {
    const float* x  = (const float*)d_in[0];   // [B,S,256] fp32
    const float* ic = (const float*)d_in[1];   // [256,5]   fp32
    const float* oc = (const float*)d_in[2];   // [256,256] fp32
    float* out = (float*)d_out;

    const int M = in_sizes[0] / KDIM;          // 65536

    cudaFuncSetAttribute(kan_main, cudaFuncAttributeMaxDynamicSharedMemorySize, SMEM_TOTAL);

    kan_prologue<<<33, 256>>>(ic, oc);
    kan_main<<<M / BM, NTHR, SMEM_TOTAL>>>(x, out);
}